// round 10
// baseline (speedup 1.0000x reference)
#include <cuda_runtime.h>
#include <math.h>

#define B_TOTAL  16384
#define F_S      48
#define T_S      512
#define N_LAYERS 16
#define TILE_R   4
#define NTILES   (B_TOTAL / TILE_R)   // 4096
#define GRID     444                  // 3 CTAs x 148 SMs, all resident
#define THREADS  256
#define DPAD     10                   // Gs/wds row stride in float2 (conflict-free)

#define NBAR(id) asm volatile("bar.sync %0, 64;" :: "r"(id) : "memory")

// ---------------- device scratch ----------------
__device__ float4 g_R4[B_TOTAL * T_S / 2];     // R state, permuted [row][tp*8+q], 64 MB
__device__ float  g_partial[T_S * GRID];       // [t][cta]
__device__ float  g_gate[T_S];
__device__ float2 c_wdT[64 * 8];               // [tp][dd] : e^{-2pi i dd tp/512}
__device__ float2 c_cb[48];                    // e^{-2pi i c b/64} / sqrt(512)
__device__ float  g_scale[2];
__device__ float  g_maxpart[256];
__device__ unsigned g_bar_count;
__device__ volatile unsigned g_bar_gen;

// ---------------- complex helpers ----------------
__device__ __forceinline__ float2 cadd(float2 a, float2 b) { return make_float2(a.x + b.x, a.y + b.y); }
__device__ __forceinline__ float2 csub(float2 a, float2 b) { return make_float2(a.x - b.x, a.y - b.y); }
__device__ __forceinline__ float2 cmul(float2 a, float2 b) {
    return make_float2(fmaf(a.x, b.x, -a.y * b.y), fmaf(a.x, b.y, a.y * b.x));
}
__device__ __forceinline__ float2 cmulj(float2 a, float2 b) {   // a * conj(b)
    return make_float2(fmaf(a.x, b.x, a.y * b.y), fmaf(a.y, b.x, -a.x * b.y));
}

#define SQ2H 0.70710678118654752f

__device__ __forceinline__ void fft8f(const float2* h, float2* X) {
    float2 ea0 = cadd(h[0], h[4]), ea1 = csub(h[0], h[4]);
    float2 eb0 = cadd(h[2], h[6]), eb1 = csub(h[2], h[6]);
    float2 oa0 = cadd(h[1], h[5]), oa1 = csub(h[1], h[5]);
    float2 ob0 = cadd(h[3], h[7]), ob1 = csub(h[3], h[7]);
    float2 E0 = cadd(ea0, eb0), E2 = csub(ea0, eb0);
    float2 mieb = make_float2(eb1.y, -eb1.x);
    float2 E1 = cadd(ea1, mieb), E3 = csub(ea1, mieb);
    float2 O0 = cadd(oa0, ob0), O2 = csub(oa0, ob0);
    float2 miob = make_float2(ob1.y, -ob1.x);
    float2 O1 = cadd(oa1, miob), O3 = csub(oa1, miob);
    X[0] = cadd(E0, O0); X[4] = csub(E0, O0);
    float2 w1o = make_float2(SQ2H * (O1.x + O1.y), SQ2H * (O1.y - O1.x));
    X[1] = cadd(E1, w1o); X[5] = csub(E1, w1o);
    float2 w2o = make_float2(O2.y, -O2.x);
    X[2] = cadd(E2, w2o); X[6] = csub(E2, w2o);
    float2 w3o = make_float2(SQ2H * (O3.y - O3.x), -SQ2H * (O3.x + O3.y));
    X[3] = cadd(E3, w3o); X[7] = csub(E3, w3o);
}

__device__ __forceinline__ void fft8i(const float2* h, float2* X) {
    float2 ea0 = cadd(h[0], h[4]), ea1 = csub(h[0], h[4]);
    float2 eb0 = cadd(h[2], h[6]), eb1 = csub(h[2], h[6]);
    float2 oa0 = cadd(h[1], h[5]), oa1 = csub(h[1], h[5]);
    float2 ob0 = cadd(h[3], h[7]), ob1 = csub(h[3], h[7]);
    float2 E0 = cadd(ea0, eb0), E2 = csub(ea0, eb0);
    float2 pieb = make_float2(-eb1.y, eb1.x);
    float2 E1 = cadd(ea1, pieb), E3 = csub(ea1, pieb);
    float2 O0 = cadd(oa0, ob0), O2 = csub(oa0, ob0);
    float2 piob = make_float2(-ob1.y, ob1.x);
    float2 O1 = cadd(oa1, piob), O3 = csub(oa1, piob);
    X[0] = cadd(E0, O0); X[4] = csub(E0, O0);
    float2 w1o = make_float2(SQ2H * (O1.x - O1.y), SQ2H * (O1.x + O1.y));
    X[1] = cadd(E1, w1o); X[5] = csub(E1, w1o);
    float2 w2o = make_float2(-O2.y, O2.x);
    X[2] = cadd(E2, w2o); X[6] = csub(E2, w2o);
    float2 w3o = make_float2(-SQ2H * (O3.x + O3.y), SQ2H * (O3.x - O3.y));
    X[3] = cadd(E3, w3o); X[7] = csub(E3, w3o);
}

// ---------------- cp.async tile prefetch (64B per thread) ----------------
__device__ __forceinline__ void cp_tile(float2* sdst, const float2* gsrc) {
    unsigned s = (unsigned)__cvta_generic_to_shared(sdst);
#pragma unroll
    for (int k = 0; k < 4; ++k)
        asm volatile("cp.async.cg.shared.global [%0], [%1], 16;"
                     :: "r"(s + 16u * k), "l"(gsrc + 2 * k) : "memory");
    asm volatile("cp.async.commit_group;" ::: "memory");
}
#define CP_WAIT() asm volatile("cp.async.wait_group 0;" ::: "memory")

// ---------------- grid barrier ----------------
__device__ __forceinline__ void grid_bar() {
    __syncthreads();
    if (threadIdx.x == 0) {
        unsigned gen = g_bar_gen;
        __threadfence();
        if (atomicAdd(&g_bar_count, 1u) == GRID - 1u) {
            g_bar_count = 0;
            __threadfence();
            g_bar_gen = gen + 1u;
        } else {
            while (g_bar_gen == gen) __nanosleep(64);
        }
        __threadfence();
    }
    __syncthreads();
}

// ---------------- max reduction ----------------
__global__ void k_max1(const float* __restrict__ u, int n) {
    float m = -INFINITY;
    for (int i = blockIdx.x * blockDim.x + threadIdx.x; i < n; i += gridDim.x * blockDim.x)
        m = fmaxf(m, u[i]);
    __shared__ float sm[256];
    sm[threadIdx.x] = m;
    __syncthreads();
    for (int s = 128; s > 0; s >>= 1) {
        if (threadIdx.x < s) sm[threadIdx.x] = fmaxf(sm[threadIdx.x], sm[threadIdx.x + s]);
        __syncthreads();
    }
    if (threadIdx.x == 0) g_maxpart[blockIdx.x] = sm[0];
}

__global__ void k_max2() {
    __shared__ float sm[256];
    sm[threadIdx.x] = g_maxpart[threadIdx.x];
    __syncthreads();
    for (int s = 128; s > 0; s >>= 1) {
        if (threadIdx.x < s) sm[threadIdx.x] = fmaxf(sm[threadIdx.x], sm[threadIdx.x + s]);
        __syncthreads();
    }
    if (threadIdx.x == 0) {
        float m = fabsf(sm[0]);
        g_scale[0] = 5.0f / m;
        g_scale[1] = m / 5.0f;
    }
}

// ---------------- tables ----------------
__global__ void k_tw() {
    int i = blockIdx.x * blockDim.x + threadIdx.x;
    if (i < 64 * 8) {
        int tp = i >> 3, dd = i & 7;
        double ang = 2.0 * M_PI * (double)(dd * tp) / 512.0;
        double s, c; sincos(ang, &s, &c);
        c_wdT[i] = make_float2((float)c, (float)(-s));
    }
    if (i < 48) {
        int cc = i >> 3, b = i & 7;
        double sc = 1.0 / sqrt(512.0);
        double ang = 2.0 * M_PI * (double)(cc * b) / 64.0;
        double s, c; sincos(ang, &s, &c);
        c_cb[i] = make_float2((float)(c * sc), (float)(-s * sc));
    }
}

// ---------------- persistent fused network kernel ----------------
__global__ void __launch_bounds__(THREADS, 3)
k_net(const float* __restrict__ u, const float* __restrict__ S1,
      const float* __restrict__ S2, float* __restrict__ out) {
    extern __shared__ float smem_raw[];
    float2* Rbuf = (float2*)smem_raw;                  // [2][4*512]  32 KB
    float2* Gs   = Rbuf + 2 * TILE_R * T_S;            // [4*64][10]  20.5 KB
    float2* wds  = Gs + TILE_R * 64 * DPAD;            // [64][10]     5 KB
    float2* cbs  = wds + 64 * DPAD;                    // [48]
    float*  gsm  = (float*)(cbs + 48);                 // [512]
    float*  ps2  = gsm + T_S;                          // [4][512]
    float*  red  = ps2 + 4 * T_S;                      // [256]

    const int tid = threadIdx.x;
    const float s_in = g_scale[0];
    const int r  = tid >> 6;
    const int tp = tid & 63;
    const int b  = tid & 7;
    const int d  = (tid >> 3) & 7;
    const int bar_id = r + 1;
    float2* g_Rf = (float2*)g_R4;

    // stage twiddle tables
    for (int i = tid; i < 64 * DPAD; i += THREADS) {
        int tpp = i / DPAD, dd = i - tpp * DPAD;
        wds[i] = (dd < 8) ? c_wdT[tpp * 8 + dd] : make_float2(0.f, 0.f);
    }
    if (tid < 48) cbs[tid] = c_cb[tid];

    float2 cbv[6];

    for (int layer = 0; layer <= N_LAYERS; ++layer) {
        const bool first = (layer == 0);
        const bool last  = (layer == N_LAYERS);
        if (!first)
            for (int i = tid; i < T_S; i += THREADS) gsm[i] = __ldcg(&g_gate[i]);
        __syncthreads();
#pragma unroll
        for (int c = 0; c < 6; ++c) cbv[c] = cbs[c * 8 + b];

        float acc[8];
#pragma unroll
        for (int q = 0; q < 8; ++q) acc[q] = 0.f;

        int par = 0;
        for (int tile = blockIdx.x; tile < NTILES; tile += GRID) {
            const int b0 = tile * TILE_R;

            CP_WAIT();
            NBAR(bar_id);          // copies visible group-wide; prev Z's Gs reads done

            // ---- stage G: hh = R*g; Gs[r][tp][dd] = wdT[tp][dd] * fft8_q(hh)[dd] ----
            float2 hh[8];
            if (!first) {
                const float4* rb = (const float4*)(Rbuf + par * (TILE_R * T_S) + r * T_S + tp * 8);
                float4 p0 = rb[0], p1 = rb[1], p2 = rb[2], p3 = rb[3];
                hh[0] = make_float2(p0.x, p0.y); hh[1] = make_float2(p0.z, p0.w);
                hh[2] = make_float2(p1.x, p1.y); hh[3] = make_float2(p1.z, p1.w);
                hh[4] = make_float2(p2.x, p2.y); hh[5] = make_float2(p2.z, p2.w);
                hh[6] = make_float2(p3.x, p3.y); hh[7] = make_float2(p3.z, p3.w);
#pragma unroll
                for (int q = 0; q < 8; ++q) {
                    float gv = gsm[(q << 6) + tp];
                    hh[q].x *= gv; hh[q].y *= gv;
                }
                float2 X[8];
                fft8f(hh, X);
                const float4* wp = (const float4*)(wds + tp * DPAD);
                float4 w01 = wp[0], w23 = wp[1], w45 = wp[2], w67 = wp[3];
                float2 y0 = cmul(X[0], make_float2(w01.x, w01.y));
                float2 y1 = cmul(X[1], make_float2(w01.z, w01.w));
                float2 y2 = cmul(X[2], make_float2(w23.x, w23.y));
                float2 y3 = cmul(X[3], make_float2(w23.z, w23.w));
                float2 y4 = cmul(X[4], make_float2(w45.x, w45.y));
                float2 y5 = cmul(X[5], make_float2(w45.z, w45.w));
                float2 y6 = cmul(X[6], make_float2(w67.x, w67.y));
                float2 y7 = cmul(X[7], make_float2(w67.z, w67.w));
                float4* gp = (float4*)(Gs + (r * 64 + tp) * DPAD);
                gp[0] = make_float4(y0.x, y0.y, y1.x, y1.y);
                gp[1] = make_float4(y2.x, y2.y, y3.x, y3.y);
                gp[2] = make_float4(y4.x, y4.y, y5.x, y5.y);
                gp[3] = make_float4(y6.x, y6.y, y7.x, y7.y);
            } else {
#pragma unroll
                for (int q = 0; q < 8; ++q) hh[q] = make_float2(0.f, 0.f);
            }

            // prefetch next tile's R (lands during A/S/Z)
            if (!first && tile + GRID < NTILES)
                cp_tile(Rbuf + (par ^ 1) * (TILE_R * T_S) + r * T_S + tp * 8,
                        g_Rf + (size_t)((tile + GRID) * TILE_R + r) * T_S + tp * 8);

            NBAR(bar_id);

            // ---- fused stage A+S (role (r,d,b)) ----
            {
                float2 p[6];
                if (!first) {
                    float2 Gv[8], A[8];
#pragma unroll
                    for (int a = 0; a < 8; ++a)
                        Gv[a] = Gs[(r * 64 + (a << 3) + b) * DPAD + d];
                    fft8f(Gv, A);
#pragma unroll
                    for (int c = 0; c < 6; ++c) p[c] = cmul(A[c], cbv[c]);
#pragma unroll
                    for (int m = 1; m < 8; m <<= 1) {
#pragma unroll
                        for (int c = 0; c < 6; ++c) {
                            p[c].x += __shfl_xor_sync(0xFFFFFFFFu, p[c].x, m);
                            p[c].y += __shfl_xor_sync(0xFFFFFFFFu, p[c].y, m);
                        }
                    }
                } else {
#pragma unroll
                    for (int c = 0; c < 6; ++c) p[c] = make_float2(0.f, 0.f);
                }

                if (last) {
                    if (b == 0) {
                        const float s_out = g_scale[1];
#pragma unroll
                        for (int c = 0; c < 6; ++c)
                            ((float2*)out)[(b0 + r) * F_S + (c << 3) + d] =
                                make_float2(p[c].x * s_out, p[c].y * s_out);
                    }
                    par ^= 1;
                    continue;
                }

                float2 v[8], S[8];
#pragma unroll
                for (int c = 0; c < 6; ++c) {
                    float2 uv = ((const float2*)u)[(b0 + r) * F_S + (c << 3) + d];
                    float2 z = make_float2(uv.x * s_in - p[c].x, uv.y * s_in - p[c].y);
                    v[c] = cmulj(z, cbv[c]);
                }
                v[6] = make_float2(0.f, 0.f);
                v[7] = make_float2(0.f, 0.f);
                fft8i(v, S);
#pragma unroll
                for (int a = 0; a < 8; ++a)
                    Gs[(r * 64 + (a << 3) + b) * DPAD + d] = S[a];
            }
            NBAR(bar_id);

            // ---- stage Z/R: Z = ifft8_d( Gs[tp][dd]*conj(wdT) ); R = hh + Z ----
            {
                const float4* gp = (const float4*)(Gs + (r * 64 + tp) * DPAD);
                const float4* wp = (const float4*)(wds + tp * DPAD);
                float4 a01 = gp[0], a23 = gp[1], a45 = gp[2], a67 = gp[3];
                float4 w01 = wp[0], w23 = wp[1], w45 = wp[2], w67 = wp[3];
                float2 v[8], Z[8];
                v[0] = cmulj(make_float2(a01.x, a01.y), make_float2(w01.x, w01.y));
                v[1] = cmulj(make_float2(a01.z, a01.w), make_float2(w01.z, w01.w));
                v[2] = cmulj(make_float2(a23.x, a23.y), make_float2(w23.x, w23.y));
                v[3] = cmulj(make_float2(a23.z, a23.w), make_float2(w23.z, w23.w));
                v[4] = cmulj(make_float2(a45.x, a45.y), make_float2(w45.x, w45.y));
                v[5] = cmulj(make_float2(a45.z, a45.w), make_float2(w45.z, w45.w));
                v[6] = cmulj(make_float2(a67.x, a67.y), make_float2(w67.x, w67.y));
                v[7] = cmulj(make_float2(a67.z, a67.w), make_float2(w67.z, w67.w));
                fft8i(v, Z);
                float4* go = (float4*)(g_Rf + (size_t)(b0 + r) * T_S + tp * 8);
#pragma unroll
                for (int q = 0; q < 8; q += 2) {
                    float R0x = Z[q].x + hh[q].x,     R0y = Z[q].y + hh[q].y;
                    float R1x = Z[q + 1].x + hh[q + 1].x, R1y = Z[q + 1].y + hh[q + 1].y;
                    go[q >> 1] = make_float4(R0x, R0y, R1x, R1y);
                    acc[q]     = fmaf(R0x, R0x, fmaf(R0y, R0y, acc[q]));
                    acc[q + 1] = fmaf(R1x, R1x, fmaf(R1y, R1y, acc[q + 1]));
                }
            }
            par ^= 1;
        }
        if (last) break;

        // prefetch first tile of next layer into buffer 0 (overlaps gate stage)
        cp_tile(Rbuf + r * T_S + tp * 8,
                g_Rf + (size_t)(blockIdx.x * TILE_R + r) * T_S + tp * 8);

        // ---- per-layer |R|^2 reduction ----
#pragma unroll
        for (int q = 0; q < 8; ++q) ps2[r * T_S + (q << 6) + tp] = acc[q];
        __syncthreads();
        for (int t = tid; t < T_S; t += THREADS)
            g_partial[t * GRID + blockIdx.x] =
                ps2[t] + ps2[T_S + t] + ps2[2 * T_S + t] + ps2[3 * T_S + t];
        grid_bar();

        // -------- gate stage --------
        for (int t = blockIdx.x; t < T_S; t += GRID) {
            float s = __ldcg(&g_partial[t * GRID + tid]);
            if (tid + 256 < GRID) s += __ldcg(&g_partial[t * GRID + tid + 256]);
            red[tid] = s;
            __syncthreads();
            for (int k = 128; k > 0; k >>= 1) {
                if (tid < k) red[tid] += red[tid + k];
                __syncthreads();
            }
            if (tid == 0) {
                float rmean = sqrtf(red[0] * (1.0f / (float)B_TOTAL));
                float x = S1[0] * (rmean - S2[0]);
                g_gate[t] = 1.0f / (1.0f + expf(-x));
            }
            __syncthreads();
        }
        grid_bar();
    }
}

// ---------------- launch ----------------
extern "C" void kernel_launch(void* const* d_in, const int* in_sizes, int n_in,
                              void* d_out, int out_size) {
    const float* u  = (const float*)d_in[0];
    const float* S1 = (const float*)d_in[1];
    const float* S2 = (const float*)d_in[2];
    float* out = (float*)d_out;

    const int smem = (2 * TILE_R * T_S + TILE_R * 64 * DPAD + 64 * DPAD + 48) * (int)sizeof(float2)
                   + (T_S + 4 * T_S + THREADS) * (int)sizeof(float);
    cudaFuncSetAttribute(k_net, cudaFuncAttributeMaxDynamicSharedMemorySize, smem);

    const int n = B_TOTAL * F_S * 2;
    k_max1<<<256, 256>>>(u, n);
    k_max2<<<1, 256>>>();
    k_tw<<<2, 256>>>();
    k_net<<<GRID, THREADS, smem>>>(u, S1, S2, out);

    (void)in_sizes; (void)n_in; (void)out_size;
}

// round 11
// speedup vs baseline: 1.0603x; 1.0603x over previous
#include <cuda_runtime.h>
#include <math.h>

#define B_TOTAL  16384
#define F_S      48
#define T_S      512
#define N_LAYERS 16
#define TILE_R   4
#define NTILES   (B_TOTAL / TILE_R)   // 4096
#define GRID     444                  // 3 CTAs x 148 SMs, all resident
#define THREADS  256
#define GPAD     72                   // float2 stride; conflict-free

#define NBAR(id) asm volatile("bar.sync %0, 64;" :: "r"(id) : "memory")

// ---------------- device scratch ----------------
__device__ float4 g_R4[B_TOTAL * T_S / 2];     // R state, permuted [row][tp*8+q], 64 MB
__device__ float  g_partial[T_S * GRID];       // [t][cta]
__device__ float  g_gate[T_S];
__device__ float2 c_wd[8 * 64];                // e^{-2pi i d tp/512}
__device__ float2 c_cb[48];                    // e^{-2pi i c b/64} / sqrt(512)
__device__ float  g_scale[2];
__device__ float  g_maxpart[256];
__device__ unsigned g_bar_count;
__device__ volatile unsigned g_bar_gen;

// ---------------- complex helpers ----------------
__device__ __forceinline__ float2 cadd(float2 a, float2 b) { return make_float2(a.x + b.x, a.y + b.y); }
__device__ __forceinline__ float2 csub(float2 a, float2 b) { return make_float2(a.x - b.x, a.y - b.y); }
__device__ __forceinline__ float2 cmul(float2 a, float2 b) {
    return make_float2(fmaf(a.x, b.x, -a.y * b.y), fmaf(a.x, b.y, a.y * b.x));
}
__device__ __forceinline__ float2 cmulj(float2 a, float2 b) {   // a * conj(b)
    return make_float2(fmaf(a.x, b.x, a.y * b.y), fmaf(a.y, b.x, -a.x * b.y));
}

#define SQ2H 0.70710678118654752f

__device__ __forceinline__ void fft8f(const float2* h, float2* X) {
    float2 ea0 = cadd(h[0], h[4]), ea1 = csub(h[0], h[4]);
    float2 eb0 = cadd(h[2], h[6]), eb1 = csub(h[2], h[6]);
    float2 oa0 = cadd(h[1], h[5]), oa1 = csub(h[1], h[5]);
    float2 ob0 = cadd(h[3], h[7]), ob1 = csub(h[3], h[7]);
    float2 E0 = cadd(ea0, eb0), E2 = csub(ea0, eb0);
    float2 mieb = make_float2(eb1.y, -eb1.x);
    float2 E1 = cadd(ea1, mieb), E3 = csub(ea1, mieb);
    float2 O0 = cadd(oa0, ob0), O2 = csub(oa0, ob0);
    float2 miob = make_float2(ob1.y, -ob1.x);
    float2 O1 = cadd(oa1, miob), O3 = csub(oa1, miob);
    X[0] = cadd(E0, O0); X[4] = csub(E0, O0);
    float2 w1o = make_float2(SQ2H * (O1.x + O1.y), SQ2H * (O1.y - O1.x));
    X[1] = cadd(E1, w1o); X[5] = csub(E1, w1o);
    float2 w2o = make_float2(O2.y, -O2.x);
    X[2] = cadd(E2, w2o); X[6] = csub(E2, w2o);
    float2 w3o = make_float2(SQ2H * (O3.y - O3.x), -SQ2H * (O3.x + O3.y));
    X[3] = cadd(E3, w3o); X[7] = csub(E3, w3o);
}

__device__ __forceinline__ void fft8i(const float2* h, float2* X) {
    float2 ea0 = cadd(h[0], h[4]), ea1 = csub(h[0], h[4]);
    float2 eb0 = cadd(h[2], h[6]), eb1 = csub(h[2], h[6]);
    float2 oa0 = cadd(h[1], h[5]), oa1 = csub(h[1], h[5]);
    float2 ob0 = cadd(h[3], h[7]), ob1 = csub(h[3], h[7]);
    float2 E0 = cadd(ea0, eb0), E2 = csub(ea0, eb0);
    float2 pieb = make_float2(-eb1.y, eb1.x);
    float2 E1 = cadd(ea1, pieb), E3 = csub(ea1, pieb);
    float2 O0 = cadd(oa0, ob0), O2 = csub(oa0, ob0);
    float2 piob = make_float2(-ob1.y, ob1.x);
    float2 O1 = cadd(oa1, piob), O3 = csub(oa1, piob);
    X[0] = cadd(E0, O0); X[4] = csub(E0, O0);
    float2 w1o = make_float2(SQ2H * (O1.x - O1.y), SQ2H * (O1.x + O1.y));
    X[1] = cadd(E1, w1o); X[5] = csub(E1, w1o);
    float2 w2o = make_float2(-O2.y, O2.x);
    X[2] = cadd(E2, w2o); X[6] = csub(E2, w2o);
    float2 w3o = make_float2(-SQ2H * (O3.x + O3.y), SQ2H * (O3.x - O3.y));
    X[3] = cadd(E3, w3o); X[7] = csub(E3, w3o);
}

// ---------------- grid barrier ----------------
__device__ __forceinline__ void grid_bar() {
    __syncthreads();
    if (threadIdx.x == 0) {
        unsigned gen = g_bar_gen;
        __threadfence();
        if (atomicAdd(&g_bar_count, 1u) == GRID - 1u) {
            g_bar_count = 0;
            __threadfence();
            g_bar_gen = gen + 1u;
        } else {
            while (g_bar_gen == gen) __nanosleep(64);
        }
        __threadfence();
    }
    __syncthreads();
}

// ---------------- max reduction ----------------
__global__ void k_max1(const float* __restrict__ u, int n) {
    float m = -INFINITY;
    for (int i = blockIdx.x * blockDim.x + threadIdx.x; i < n; i += gridDim.x * blockDim.x)
        m = fmaxf(m, u[i]);
    __shared__ float sm[256];
    sm[threadIdx.x] = m;
    __syncthreads();
    for (int s = 128; s > 0; s >>= 1) {
        if (threadIdx.x < s) sm[threadIdx.x] = fmaxf(sm[threadIdx.x], sm[threadIdx.x + s]);
        __syncthreads();
    }
    if (threadIdx.x == 0) g_maxpart[blockIdx.x] = sm[0];
}

__global__ void k_max2() {
    __shared__ float sm[256];
    sm[threadIdx.x] = g_maxpart[threadIdx.x];
    __syncthreads();
    for (int s = 128; s > 0; s >>= 1) {
        if (threadIdx.x < s) sm[threadIdx.x] = fmaxf(sm[threadIdx.x], sm[threadIdx.x + s]);
        __syncthreads();
    }
    if (threadIdx.x == 0) {
        float m = fabsf(sm[0]);
        g_scale[0] = 5.0f / m;
        g_scale[1] = m / 5.0f;
    }
}

// ---------------- tables ----------------
__global__ void k_tw() {
    int i = blockIdx.x * blockDim.x + threadIdx.x;
    if (i < 8 * 64) {
        int d = i >> 6, tp = i & 63;
        double ang = 2.0 * M_PI * (double)(d * tp) / 512.0;
        double s, c; sincos(ang, &s, &c);
        c_wd[i] = make_float2((float)c, (float)(-s));
    }
    if (i < 48) {
        int cc = i >> 3, b = i & 7;
        double sc = 1.0 / sqrt(512.0);
        double ang = 2.0 * M_PI * (double)(cc * b) / 64.0;
        double s, c; sincos(ang, &s, &c);
        c_cb[i] = make_float2((float)(c * sc), (float)(-s * sc));
    }
}

// ---------------- persistent fused network kernel ----------------
extern __shared__ float smem_raw[];

__global__ void __launch_bounds__(THREADS, 3)
k_net(const float* __restrict__ u, const float* __restrict__ S1,
      const float* __restrict__ S2, float* __restrict__ out) {
    float2* Gs   = (float2*)smem_raw;                  // [32][GPAD]  18.4 KB
    float2* wds  = Gs + 32 * GPAD;                     // [512]        4 KB
    float2* cbs  = wds + 8 * 64;                       // [48]         0.4 KB
    float*  gsm  = (float*)(cbs + 48);                 // [512]        2 KB
    float*  ps2  = gsm + T_S;                          // [4][512]     8 KB
    float*  red  = ps2 + 4 * T_S;                      // [256]        1 KB

    const int tid = threadIdx.x;
    const float s_in = g_scale[0];
    const int r  = tid >> 6;          // row within tile
    const int tp = tid & 63;          // G/Z-stage time-within-64
    const int b  = tid & 7;           // A/S-stage radix lane
    const int d  = (tid >> 3) & 7;    // A/S-stage digit
    const int bar_id = r + 1;

    // stage twiddle tables into smem
    for (int i = tid; i < 8 * 64; i += THREADS) wds[i] = c_wd[i];
    if (tid < 48) cbs[tid] = c_cb[tid];

    float2 cbv[6];

    for (int layer = 0; layer <= N_LAYERS; ++layer) {
        const bool first = (layer == 0);
        const bool last  = (layer == N_LAYERS);
        if (!first) {
            for (int i = tid; i < T_S; i += THREADS) gsm[i] = __ldcg(&g_gate[i]);
        }
        __syncthreads();
#pragma unroll
        for (int c = 0; c < 6; ++c) cbv[c] = cbs[c * 8 + b];

        float acc[8];                              // per-thread |R|^2 partials, regs
#pragma unroll
        for (int q = 0; q < 8; ++q) acc[q] = 0.f;

        for (int tile = blockIdx.x; tile < NTILES; tile += GRID) {
            const int b0 = tile * TILE_R;
            // permuted R base for this thread: row (b0+r), elements tp*8..tp*8+7
            const size_t rbase = ((size_t)(b0 + r) * T_S + tp * 8) >> 1;   // float4 index

            // ---- stage G: hh = R*g (regs); Gs[r][dd][tp] = wd[dd][tp] * fft8_q(hh) ----
            float2 hh[8];
            if (!first) {
                float4 p0 = __ldcg(&g_R4[rbase + 0]);
                float4 p1 = __ldcg(&g_R4[rbase + 1]);
                float4 p2 = __ldcg(&g_R4[rbase + 2]);
                float4 p3 = __ldcg(&g_R4[rbase + 3]);
                hh[0] = make_float2(p0.x, p0.y); hh[1] = make_float2(p0.z, p0.w);
                hh[2] = make_float2(p1.x, p1.y); hh[3] = make_float2(p1.z, p1.w);
                hh[4] = make_float2(p2.x, p2.y); hh[5] = make_float2(p2.z, p2.w);
                hh[6] = make_float2(p3.x, p3.y); hh[7] = make_float2(p3.z, p3.w);
#pragma unroll
                for (int q = 0; q < 8; ++q) {
                    float gv = gsm[(q << 6) + tp];
                    hh[q].x *= gv; hh[q].y *= gv;
                }
                float2 X[8];
                fft8f(hh, X);
#pragma unroll
                for (int dd = 0; dd < 8; ++dd)
                    Gs[(r * 8 + dd) * GPAD + tp] = cmul(X[dd], wds[(dd << 6) + tp]);
            } else {
#pragma unroll
                for (int q = 0; q < 8; ++q) hh[q] = make_float2(0.f, 0.f);
            }
            NBAR(bar_id);

            // ---- fused stage A+S (role (r,d,b)) ----
            {
                float2 p[6];
                if (!first) {
                    float2 Gv[8], A[8];
#pragma unroll
                    for (int a = 0; a < 8; ++a) Gv[a] = Gs[(r * 8 + d) * GPAD + (a << 3) + b];
                    fft8f(Gv, A);
#pragma unroll
                    for (int c = 0; c < 6; ++c) p[c] = cmul(A[c], cbv[c]);
#pragma unroll
                    for (int m = 1; m < 8; m <<= 1) {
#pragma unroll
                        for (int c = 0; c < 6; ++c) {
                            p[c].x += __shfl_xor_sync(0xFFFFFFFFu, p[c].x, m);
                            p[c].y += __shfl_xor_sync(0xFFFFFFFFu, p[c].y, m);
                        }
                    }
                } else {
#pragma unroll
                    for (int c = 0; c < 6; ++c) p[c] = make_float2(0.f, 0.f);
                }

                if (last) {
                    if (b == 0) {
                        const float s_out = g_scale[1];
#pragma unroll
                        for (int c = 0; c < 6; ++c)
                            ((float2*)out)[(b0 + r) * F_S + (c << 3) + d] =
                                make_float2(p[c].x * s_out, p[c].y * s_out);
                    }
                    NBAR(bar_id);          // protect Gs reuse by next tile's G stage
                    continue;
                }

                float2 v[8], S[8];
#pragma unroll
                for (int c = 0; c < 6; ++c) {
                    float2 uv = ((const float2*)u)[(b0 + r) * F_S + (c << 3) + d];
                    float2 z = make_float2(uv.x * s_in - p[c].x, uv.y * s_in - p[c].y);
                    v[c] = cmulj(z, cbv[c]);
                }
                v[6] = make_float2(0.f, 0.f);
                v[7] = make_float2(0.f, 0.f);
                fft8i(v, S);
#pragma unroll
                for (int a = 0; a < 8; ++a)
                    Gs[(r * 8 + d) * GPAD + (a << 3) + b] = S[a];
            }
            NBAR(bar_id);

            // ---- stage Z/R: Z = ifft8_d( Gs[d][tp] * conj(wd[d][tp]) ); R = hh + Z ----
            {
                float2 v[8], Z[8];
#pragma unroll
                for (int dd = 0; dd < 8; ++dd)
                    v[dd] = cmulj(Gs[(r * 8 + dd) * GPAD + tp], wds[(dd << 6) + tp]);
                fft8i(v, Z);
#pragma unroll
                for (int q = 0; q < 8; q += 2) {
                    float R0x = Z[q].x + hh[q].x,         R0y = Z[q].y + hh[q].y;
                    float R1x = Z[q + 1].x + hh[q + 1].x, R1y = Z[q + 1].y + hh[q + 1].y;
                    g_R4[rbase + (q >> 1)] = make_float4(R0x, R0y, R1x, R1y);
                    acc[q]     = fmaf(R0x, R0x, fmaf(R0y, R0y, acc[q]));
                    acc[q + 1] = fmaf(R1x, R1x, fmaf(R1y, R1y, acc[q + 1]));
                }
            }
            NBAR(bar_id);                  // protect Gs reuse by next tile's G stage
        }
        if (last) break;

        // ---- per-layer |R|^2 reduction: regs -> smem (r groups) -> per-CTA partial ----
#pragma unroll
        for (int q = 0; q < 8; ++q) ps2[r * T_S + (q << 6) + tp] = acc[q];
        __syncthreads();
        for (int t = tid; t < T_S; t += THREADS)
            g_partial[t * GRID + blockIdx.x] =
                ps2[t] + ps2[T_S + t] + ps2[2 * T_S + t] + ps2[3 * T_S + t];
        grid_bar();

        // -------- gate stage --------
        for (int t = blockIdx.x; t < T_S; t += GRID) {
            float s = __ldcg(&g_partial[t * GRID + tid]);
            if (tid + 256 < GRID) s += __ldcg(&g_partial[t * GRID + tid + 256]);
            red[tid] = s;
            __syncthreads();
            for (int k = 128; k > 0; k >>= 1) {
                if (tid < k) red[tid] += red[tid + k];
                __syncthreads();
            }
            if (tid == 0) {
                float rmean = sqrtf(red[0] * (1.0f / (float)B_TOTAL));
                float x = S1[0] * (rmean - S2[0]);
                g_gate[t] = 1.0f / (1.0f + expf(-x));
            }
            __syncthreads();
        }
        grid_bar();
    }
}

// ---------------- launch ----------------
extern "C" void kernel_launch(void* const* d_in, const int* in_sizes, int n_in,
                              void* d_out, int out_size) {
    const float* u  = (const float*)d_in[0];
    const float* S1 = (const float*)d_in[1];
    const float* S2 = (const float*)d_in[2];
    float* out = (float*)d_out;

    const int smem = (32 * GPAD + 8 * 64 + 48) * (int)sizeof(float2)
                   + (T_S + 4 * T_S + THREADS) * (int)sizeof(float);
    cudaFuncSetAttribute(k_net, cudaFuncAttributeMaxDynamicSharedMemorySize, smem);

    const int n = B_TOTAL * F_S * 2;
    k_max1<<<256, 256>>>(u, n);
    k_max2<<<1, 256>>>();
    k_tw<<<2, 256>>>();
    k_net<<<GRID, THREADS, smem>>>(u, S1, S2, out);

    (void)in_sizes; (void)n_in; (void)out_size;
}

// round 12
// speedup vs baseline: 1.4679x; 1.3844x over previous
#include <cuda_runtime.h>
#include <math.h>

#define B_TOTAL  16384
#define F_S      48
#define T_S      512
#define N_LAYERS 16
#define TILE_R   4
#define NTILES   (B_TOTAL / TILE_R)   // 4096
#define GRID     444                  // 3 CTAs x 148 SMs, all resident
#define THREADS  256
#define GPAD     72                   // float2 stride; conflict-free
#define GSIZE    (32 * GPAD)          // one Gs buffer (float2 count)

#define NBAR(id) asm volatile("bar.sync %0, 64;" :: "r"(id) : "memory")

// ---------------- device scratch ----------------
__device__ float2 g_R[B_TOTAL * T_S];          // 64 MB state (L2-resident)
__device__ float  g_partial[T_S * GRID];       // [t][cta]
__device__ float  g_gate[T_S];
__device__ float2 c_wd[8 * 64];                // e^{-2pi i d tp/512}
__device__ float2 c_cb[48];                    // e^{-2pi i c b/64} / sqrt(512)
__device__ float  g_scale[2];
__device__ float  g_maxpart[256];
__device__ unsigned g_bar_count;
__device__ volatile unsigned g_bar_gen;

// ---------------- complex helpers ----------------
__device__ __forceinline__ float2 cadd(float2 a, float2 b) { return make_float2(a.x + b.x, a.y + b.y); }
__device__ __forceinline__ float2 csub(float2 a, float2 b) { return make_float2(a.x - b.x, a.y - b.y); }
__device__ __forceinline__ float2 cmul(float2 a, float2 b) {
    return make_float2(fmaf(a.x, b.x, -a.y * b.y), fmaf(a.x, b.y, a.y * b.x));
}
__device__ __forceinline__ float2 cmulj(float2 a, float2 b) {   // a * conj(b)
    return make_float2(fmaf(a.x, b.x, a.y * b.y), fmaf(a.y, b.x, -a.x * b.y));
}

#define SQ2H 0.70710678118654752f

__device__ __forceinline__ void fft8f(const float2* h, float2* X) {
    float2 ea0 = cadd(h[0], h[4]), ea1 = csub(h[0], h[4]);
    float2 eb0 = cadd(h[2], h[6]), eb1 = csub(h[2], h[6]);
    float2 oa0 = cadd(h[1], h[5]), oa1 = csub(h[1], h[5]);
    float2 ob0 = cadd(h[3], h[7]), ob1 = csub(h[3], h[7]);
    float2 E0 = cadd(ea0, eb0), E2 = csub(ea0, eb0);
    float2 mieb = make_float2(eb1.y, -eb1.x);
    float2 E1 = cadd(ea1, mieb), E3 = csub(ea1, mieb);
    float2 O0 = cadd(oa0, ob0), O2 = csub(oa0, ob0);
    float2 miob = make_float2(ob1.y, -ob1.x);
    float2 O1 = cadd(oa1, miob), O3 = csub(oa1, miob);
    X[0] = cadd(E0, O0); X[4] = csub(E0, O0);
    float2 w1o = make_float2(SQ2H * (O1.x + O1.y), SQ2H * (O1.y - O1.x));
    X[1] = cadd(E1, w1o); X[5] = csub(E1, w1o);
    float2 w2o = make_float2(O2.y, -O2.x);
    X[2] = cadd(E2, w2o); X[6] = csub(E2, w2o);
    float2 w3o = make_float2(SQ2H * (O3.y - O3.x), -SQ2H * (O3.x + O3.y));
    X[3] = cadd(E3, w3o); X[7] = csub(E3, w3o);
}

__device__ __forceinline__ void fft8i(const float2* h, float2* X) {
    float2 ea0 = cadd(h[0], h[4]), ea1 = csub(h[0], h[4]);
    float2 eb0 = cadd(h[2], h[6]), eb1 = csub(h[2], h[6]);
    float2 oa0 = cadd(h[1], h[5]), oa1 = csub(h[1], h[5]);
    float2 ob0 = cadd(h[3], h[7]), ob1 = csub(h[3], h[7]);
    float2 E0 = cadd(ea0, eb0), E2 = csub(ea0, eb0);
    float2 pieb = make_float2(-eb1.y, eb1.x);
    float2 E1 = cadd(ea1, pieb), E3 = csub(ea1, pieb);
    float2 O0 = cadd(oa0, ob0), O2 = csub(oa0, ob0);
    float2 piob = make_float2(-ob1.y, ob1.x);
    float2 O1 = cadd(oa1, piob), O3 = csub(oa1, piob);
    X[0] = cadd(E0, O0); X[4] = csub(E0, O0);
    float2 w1o = make_float2(SQ2H * (O1.x - O1.y), SQ2H * (O1.x + O1.y));
    X[1] = cadd(E1, w1o); X[5] = csub(E1, w1o);
    float2 w2o = make_float2(-O2.y, O2.x);
    X[2] = cadd(E2, w2o); X[6] = csub(E2, w2o);
    float2 w3o = make_float2(-SQ2H * (O3.x + O3.y), SQ2H * (O3.x - O3.y));
    X[3] = cadd(E3, w3o); X[7] = csub(E3, w3o);
}

// ---------------- grid barrier ----------------
__device__ __forceinline__ void grid_bar() {
    __syncthreads();
    if (threadIdx.x == 0) {
        unsigned gen = g_bar_gen;
        __threadfence();
        if (atomicAdd(&g_bar_count, 1u) == GRID - 1u) {
            g_bar_count = 0;
            __threadfence();
            g_bar_gen = gen + 1u;
        } else {
            while (g_bar_gen == gen) __nanosleep(64);
        }
        __threadfence();
    }
    __syncthreads();
}

// ---------------- max reduction ----------------
__global__ void k_max1(const float* __restrict__ u, int n) {
    float m = -INFINITY;
    for (int i = blockIdx.x * blockDim.x + threadIdx.x; i < n; i += gridDim.x * blockDim.x)
        m = fmaxf(m, u[i]);
    __shared__ float sm[256];
    sm[threadIdx.x] = m;
    __syncthreads();
    for (int s = 128; s > 0; s >>= 1) {
        if (threadIdx.x < s) sm[threadIdx.x] = fmaxf(sm[threadIdx.x], sm[threadIdx.x + s]);
        __syncthreads();
    }
    if (threadIdx.x == 0) g_maxpart[blockIdx.x] = sm[0];
}

__global__ void k_max2() {
    __shared__ float sm[256];
    sm[threadIdx.x] = g_maxpart[threadIdx.x];
    __syncthreads();
    for (int s = 128; s > 0; s >>= 1) {
        if (threadIdx.x < s) sm[threadIdx.x] = fmaxf(sm[threadIdx.x], sm[threadIdx.x + s]);
        __syncthreads();
    }
    if (threadIdx.x == 0) {
        float m = fabsf(sm[0]);
        g_scale[0] = 5.0f / m;
        g_scale[1] = m / 5.0f;
    }
}

// ---------------- tables ----------------
__global__ void k_tw() {
    int i = blockIdx.x * blockDim.x + threadIdx.x;
    if (i < 8 * 64) {
        int d = i >> 6, tp = i & 63;
        double ang = 2.0 * M_PI * (double)(d * tp) / 512.0;
        double s, c; sincos(ang, &s, &c);
        c_wd[i] = make_float2((float)c, (float)(-s));
    }
    if (i < 48) {
        int cc = i >> 3, b = i & 7;
        double sc = 1.0 / sqrt(512.0);
        double ang = 2.0 * M_PI * (double)(cc * b) / 64.0;
        double s, c; sincos(ang, &s, &c);
        c_cb[i] = make_float2((float)(c * sc), (float)(-s * sc));
    }
}

// ---------------- persistent fused network kernel ----------------
extern __shared__ float smem_raw[];

__global__ void __launch_bounds__(THREADS, 3)
k_net(const float* __restrict__ u, const float* __restrict__ S1,
      const float* __restrict__ S2, float* __restrict__ out) {
    float2* Gs   = (float2*)smem_raw;                  // [2][32][GPAD] 36.9 KB
    float2* wds  = Gs + 2 * GSIZE;                     // [512]          4 KB
    float2* cbs  = wds + 8 * 64;                       // [48]           0.4 KB
    float*  ps2  = (float*)(cbs + 48);                 // [4][512]       8 KB
    float*  red  = ps2 + 4 * T_S;                      // [256]          1 KB

    const int tid = threadIdx.x;
    const float s_in = g_scale[0];
    const int r  = tid >> 6;          // row within tile
    const int tp = tid & 63;          // G/Z-stage time-within-64
    const int b  = tid & 7;           // A/S-stage radix lane
    const int d  = (tid >> 3) & 7;    // A/S-stage digit
    const int bar_id = r + 1;

    // stage twiddle tables into smem
    for (int i = tid; i < 8 * 64; i += THREADS) wds[i] = c_wd[i];
    if (tid < 48) cbs[tid] = c_cb[tid];
    __syncthreads();

    float2 cbv[6];
#pragma unroll
    for (int c = 0; c < 6; ++c) cbv[c] = cbs[c * 8 + b];

    for (int layer = 0; layer <= N_LAYERS; ++layer) {
        const bool first = (layer == 0);
        const bool last  = (layer == N_LAYERS);

        // gate values this thread needs, in registers (t = 64q + tp)
        float gvv[8];
        if (!first) {
#pragma unroll
            for (int q = 0; q < 8; ++q) gvv[q] = __ldcg(&g_gate[(q << 6) + tp]);
        }

        float acc[8];                              // per-thread |R|^2 partials
#pragma unroll
        for (int q = 0; q < 8; ++q) acc[q] = 0.f;

        int par = 0;
        for (int tile = blockIdx.x; tile < NTILES; tile += GRID) {
            const int b0 = tile * TILE_R;
            float2* Gb = Gs + par * GSIZE;

            // ---- stage G: hh = R*g (regs); Gb[r][dd][tp] = wd[dd][tp] * fft8_q(hh) ----
            float2 hh[8];
            if (!first) {
                float2 X[8];
#pragma unroll
                for (int q = 0; q < 8; ++q) {
                    float2 Rv = __ldcg(&g_R[(b0 + r) * T_S + (q << 6) + tp]);
                    hh[q] = make_float2(Rv.x * gvv[q], Rv.y * gvv[q]);
                }
                fft8f(hh, X);
#pragma unroll
                for (int dd = 0; dd < 8; ++dd)
                    Gb[(r * 8 + dd) * GPAD + tp] = cmul(X[dd], wds[(dd << 6) + tp]);
            } else {
#pragma unroll
                for (int q = 0; q < 8; ++q) hh[q] = make_float2(0.f, 0.f);
            }
            NBAR(bar_id);

            // ---- fused stage A+S (role (r,d,b)) ----
            {
                float2 p[6];
                if (!first) {
                    float2 Gv[8], A[8];
#pragma unroll
                    for (int a = 0; a < 8; ++a) Gv[a] = Gb[(r * 8 + d) * GPAD + (a << 3) + b];
                    fft8f(Gv, A);
#pragma unroll
                    for (int c = 0; c < 6; ++c) p[c] = cmul(A[c], cbv[c]);
#pragma unroll
                    for (int m = 1; m < 8; m <<= 1) {
#pragma unroll
                        for (int c = 0; c < 6; ++c) {
                            p[c].x += __shfl_xor_sync(0xFFFFFFFFu, p[c].x, m);
                            p[c].y += __shfl_xor_sync(0xFFFFFFFFu, p[c].y, m);
                        }
                    }
                } else {
#pragma unroll
                    for (int c = 0; c < 6; ++c) p[c] = make_float2(0.f, 0.f);
                }

                if (last) {
                    if (b == 0) {
                        const float s_out = g_scale[1];
#pragma unroll
                        for (int c = 0; c < 6; ++c)
                            ((float2*)out)[(b0 + r) * F_S + (c << 3) + d] =
                                make_float2(p[c].x * s_out, p[c].y * s_out);
                    }
                    par ^= 1;      // double buffer: next G writes other half, no barrier
                    continue;
                }

                float2 v[8], S[8];
#pragma unroll
                for (int c = 0; c < 6; ++c) {
                    float2 uv = ((const float2*)u)[(b0 + r) * F_S + (c << 3) + d];
                    float2 z = make_float2(uv.x * s_in - p[c].x, uv.y * s_in - p[c].y);
                    v[c] = cmulj(z, cbv[c]);
                }
                v[6] = make_float2(0.f, 0.f);
                v[7] = make_float2(0.f, 0.f);
                fft8i(v, S);
#pragma unroll
                for (int a = 0; a < 8; ++a)
                    Gb[(r * 8 + d) * GPAD + (a << 3) + b] = S[a];   // same slots this thread read
            }
            NBAR(bar_id);

            // ---- stage Z/R: Z = ifft8_d( Gb[d][tp] * conj(wd[d][tp]) ); R = hh + Z ----
            {
                float2 v[8], Z[8];
#pragma unroll
                for (int dd = 0; dd < 8; ++dd)
                    v[dd] = cmulj(Gb[(r * 8 + dd) * GPAD + tp], wds[(dd << 6) + tp]);
                fft8i(v, Z);
#pragma unroll
                for (int q = 0; q < 8; ++q) {
                    float Rr = Z[q].x + hh[q].x;
                    float Ri = Z[q].y + hh[q].y;
                    g_R[(b0 + r) * T_S + (q << 6) + tp] = make_float2(Rr, Ri);
                    acc[q] = fmaf(Rr, Rr, fmaf(Ri, Ri, acc[q]));
                }
            }
            par ^= 1;              // double buffer: next G writes other half, no barrier
        }
        if (last) break;

        // ---- per-layer |R|^2 reduction: regs -> smem (r groups) -> per-CTA partial ----
#pragma unroll
        for (int q = 0; q < 8; ++q) ps2[r * T_S + (q << 6) + tp] = acc[q];
        __syncthreads();
        for (int t = tid; t < T_S; t += THREADS)
            g_partial[t * GRID + blockIdx.x] =
                ps2[t] + ps2[T_S + t] + ps2[2 * T_S + t] + ps2[3 * T_S + t];
        grid_bar();

        // -------- gate stage --------
        for (int t = blockIdx.x; t < T_S; t += GRID) {
            float s = __ldcg(&g_partial[t * GRID + tid]);
            if (tid + 256 < GRID) s += __ldcg(&g_partial[t * GRID + tid + 256]);
            red[tid] = s;
            __syncthreads();
            for (int k = 128; k > 0; k >>= 1) {
                if (tid < k) red[tid] += red[tid + k];
                __syncthreads();
            }
            if (tid == 0) {
                float rmean = sqrtf(red[0] * (1.0f / (float)B_TOTAL));
                float x = S1[0] * (rmean - S2[0]);
                g_gate[t] = 1.0f / (1.0f + expf(-x));
            }
            __syncthreads();
        }
        grid_bar();
    }
}

// ---------------- launch ----------------
extern "C" void kernel_launch(void* const* d_in, const int* in_sizes, int n_in,
                              void* d_out, int out_size) {
    const float* u  = (const float*)d_in[0];
    const float* S1 = (const float*)d_in[1];
    const float* S2 = (const float*)d_in[2];
    float* out = (float*)d_out;

    const int smem = (2 * GSIZE + 8 * 64 + 48) * (int)sizeof(float2)
                   + (4 * T_S + THREADS) * (int)sizeof(float);
    cudaFuncSetAttribute(k_net, cudaFuncAttributeMaxDynamicSharedMemorySize, smem);

    const int n = B_TOTAL * F_S * 2;
    k_max1<<<256, 256>>>(u, n);
    k_max2<<<1, 256>>>();
    k_tw<<<2, 256>>>();
    k_net<<<GRID, THREADS, smem>>>(u, S1, S2, out);

    (void)in_sizes; (void)n_in; (void)out_size;
}